// round 13
// baseline (speedup 1.0000x reference)
#include <cuda_runtime.h>
#include <cstdint>

// 2-layer GRU encoder, fused. R11: homogeneous thread pool (no warp
// specialization): every thread does layer-1 phase then layer-2 phase per step,
// separated by plain __syncthreads(). Butterfly shfl reductions (redux.f32 is
// not supported on sm_103). Weights stay in registers, f32x2 FMA throughout.
// B=1024, T=1024, H1=64, H2=32. Grid 256 x 256 threads, 2 CTAs/SM, NB=4.

#define T_STEPS 1024
#define NBATCH  1024
#define H1DIM   64
#define H2DIM   32
#define NB      4      // batch rows per block
#define NTHREADS 256

__device__ __forceinline__ void fma2(uint64_t &acc, uint64_t a, uint64_t b) {
    asm("fma.rn.f32x2 %0, %1, %2, %0;" : "+l"(acc) : "l"(a), "l"(b));
}
__device__ __forceinline__ float hadd2(uint64_t v) {
    float lo, hi;
    asm("mov.b64 {%0,%1}, %2;" : "=f"(lo), "=f"(hi) : "l"(v));
    return lo + hi;
}
__device__ __forceinline__ float sigf(float x) {
    return __fdividef(1.0f, 1.0f + __expf(-x));
}
__device__ __forceinline__ float tanhf_fast(float x) {
    return fmaf(2.0f, sigf(2.0f * x), -1.0f);   // safe at both infinities
}

__global__ void __launch_bounds__(NTHREADS, 2)
gru2_fused_kernel(const float* __restrict__ x,
                  const float* __restrict__ Wih1, const float* __restrict__ Whh1,
                  const float* __restrict__ bih1, const float* __restrict__ bhh1,
                  const float* __restrict__ Wih2, const float* __restrict__ Whh2,
                  const float* __restrict__ bih2, const float* __restrict__ bhh2,
                  float* __restrict__ out)
{
    __shared__ __align__(16) float xs[NB][T_STEPS];      // 16 KB x slab
    __shared__ __align__(16) float h1s[2][NB][H1DIM];    // double-buffered h1
    __shared__ __align__(16) float h2s[2][NB][H2DIM];    // double-buffered h2

    const int tid = threadIdx.x;
    const int b0  = blockIdx.x * NB;

    // ---- phase-1 identity: (j, kq) ; k pairs {kq + 4p}, p in [0,8) ----
    const int kq = tid & 3;
    const int j  = tid >> 2;
    // ---- phase-2 identity: (j2, s) ; k pairs {s + 8p} ----
    const int s  = tid & 7;
    const int j2 = tid >> 3;

    // --- load x slab (coalesced float4) + zero h buffers ---
    for (int i = tid; i < NB * T_STEPS / 4; i += NTHREADS) {
        int row = i / (T_STEPS / 4);
        int col = i % (T_STEPS / 4);
        reinterpret_cast<float4*>(xs[row])[col] =
            reinterpret_cast<const float4*>(x + (size_t)(b0 + row) * T_STEPS)[col];
    }
    for (int i = tid; i < 2 * NB * H1DIM; i += NTHREADS) (&h1s[0][0][0])[i] = 0.0f;
    for (int i = tid; i < 2 * NB * H2DIM; i += NTHREADS) (&h2s[0][0][0])[i] = 0.0f;

    // ---- weights in registers ----
    // layer 1: rows (j, j+64, j+128) of Whh1, pairs {kq+4p}
    uint64_t w1[3][8];
    #pragma unroll
    for (int g = 0; g < 3; g++) {
        const float* row = Whh1 + (size_t)(j + 64 * g) * 64;
        #pragma unroll
        for (int p = 0; p < 8; p++)
            w1[g][p] = *reinterpret_cast<const uint64_t*>(row + 2 * (kq + 4 * p));
    }
    const float wir = Wih1[j], wiz = Wih1[j + 64], win = Wih1[j + 128];
    const float br  = bih1[j]      + bhh1[j];
    const float bz  = bih1[j + 64] + bhh1[j + 64];
    const float bni = bih1[j + 128];
    const float bnh = bhh1[j + 128];

    // layer 2: rows (j2, j2+32, j2+64); ih pairs {s+8p} p<4, hh pairs {s+8p} p<2
    uint64_t wI[3][4], wH[3][2];
    #pragma unroll
    for (int g = 0; g < 3; g++) {
        const float* ri = Wih2 + (size_t)(j2 + 32 * g) * 64;
        #pragma unroll
        for (int p = 0; p < 4; p++)
            wI[g][p] = *reinterpret_cast<const uint64_t*>(ri + 2 * (s + 8 * p));
        const float* rh = Whh2 + (size_t)(j2 + 32 * g) * 32;
        #pragma unroll
        for (int p = 0; p < 2; p++)
            wH[g][p] = *reinterpret_cast<const uint64_t*>(rh + 2 * (s + 8 * p));
    }
    const float br2  = bih2[j2]      + bhh2[j2];
    const float bz2  = bih2[j2 + 32] + bhh2[j2 + 32];
    const float bn2i = bih2[j2 + 64];
    const float bn2h = bhh2[j2 + 64];

    __syncthreads();

    int rp = 0, q = 0;
    for (int it = 0; it < T_STEPS; ++it) {
        // ================= PHASE 1: layer-1 step it =================
        // reads h1s[rp] (= out1[it-1]), writes h1s[rp^1] (= out1[it])
        #pragma unroll 2
        for (int b = 0; b < NB; b++) {
            uint64_t aR = 0, aZ = 0, aN = 0;
            #pragma unroll
            for (int p = 0; p < 8; p++) {
                uint64_t hv = *reinterpret_cast<const uint64_t*>(
                    &h1s[rp][b][2 * (kq + 4 * p)]);
                fma2(aR, w1[0][p], hv);
                fma2(aZ, w1[1][p], hv);
                fma2(aN, w1[2][p], hv);
            }
            float sR = hadd2(aR);
            sR += __shfl_xor_sync(0xffffffffu, sR, 1);
            sR += __shfl_xor_sync(0xffffffffu, sR, 2);
            float sZ = hadd2(aZ);
            sZ += __shfl_xor_sync(0xffffffffu, sZ, 1);
            sZ += __shfl_xor_sync(0xffffffffu, sZ, 2);
            float sN = hadd2(aN);
            sN += __shfl_xor_sync(0xffffffffu, sN, 1);
            sN += __shfl_xor_sync(0xffffffffu, sN, 2);
            if (kq == b) {                 // one lane per (j, b) finalizes
                float xv  = xs[b][it];
                float r   = sigf(fmaf(wir, xv, sR + br));
                float z   = sigf(fmaf(wiz, xv, sZ + bz));
                float gxn = fmaf(win, xv, bni);
                float n   = tanhf_fast(fmaf(r, sN + bnh, gxn));
                float ho  = h1s[rp][b][j];
                h1s[rp ^ 1][b][j] = n + z * (ho - n);
            }
        }
        __syncthreads();

        // ================= PHASE 2: layer-2 step it =================
        // reads h1s[rp^1] (= out1[it]) and h2s[q], writes h2s[q^1]
        #pragma unroll 2
        for (int b = 0; b < NB; b++) {
            uint64_t aR = 0, aZ = 0, aNI = 0, aNH = 0;
            #pragma unroll
            for (int p = 0; p < 4; p++) {
                uint64_t hv = *reinterpret_cast<const uint64_t*>(
                    &h1s[rp ^ 1][b][2 * (s + 8 * p)]);
                fma2(aR,  wI[0][p], hv);
                fma2(aZ,  wI[1][p], hv);
                fma2(aNI, wI[2][p], hv);
            }
            #pragma unroll
            for (int p = 0; p < 2; p++) {
                uint64_t hv = *reinterpret_cast<const uint64_t*>(
                    &h2s[q][b][2 * (s + 8 * p)]);
                fma2(aR,  wH[0][p], hv);
                fma2(aZ,  wH[1][p], hv);
                fma2(aNH, wH[2][p], hv);
            }
            float sR  = hadd2(aR);
            sR  += __shfl_xor_sync(0xffffffffu, sR, 1);
            sR  += __shfl_xor_sync(0xffffffffu, sR, 2);
            sR  += __shfl_xor_sync(0xffffffffu, sR, 4);
            float sZ  = hadd2(aZ);
            sZ  += __shfl_xor_sync(0xffffffffu, sZ, 1);
            sZ  += __shfl_xor_sync(0xffffffffu, sZ, 2);
            sZ  += __shfl_xor_sync(0xffffffffu, sZ, 4);
            float sNI = hadd2(aNI);
            sNI += __shfl_xor_sync(0xffffffffu, sNI, 1);
            sNI += __shfl_xor_sync(0xffffffffu, sNI, 2);
            sNI += __shfl_xor_sync(0xffffffffu, sNI, 4);
            float sNH = hadd2(aNH);
            sNH += __shfl_xor_sync(0xffffffffu, sNH, 1);
            sNH += __shfl_xor_sync(0xffffffffu, sNH, 2);
            sNH += __shfl_xor_sync(0xffffffffu, sNH, 4);
            if (s == b) {                  // one lane per (j2, b) finalizes
                float r  = sigf(sR + br2);
                float z  = sigf(sZ + bz2);
                float n  = tanhf_fast(sNI + bn2i + r * (sNH + bn2h));
                float ho = h2s[q][b][j2];
                float hn = n + z * (ho - n);
                h2s[q ^ 1][b][j2] = hn;
                if (it == T_STEPS - 1)
                    out[(size_t)(b0 + b) * H2DIM + j2] = hn;
            }
        }
        __syncthreads();

        rp ^= 1;
        q  ^= 1;
    }
}

extern "C" void kernel_launch(void* const* d_in, const int* in_sizes, int n_in,
                              void* d_out, int out_size) {
    const float* x    = (const float*)d_in[0];   // [1024,1024]
    const float* Wih1 = (const float*)d_in[1];   // [192,1]
    const float* Whh1 = (const float*)d_in[2];   // [192,64]
    const float* bih1 = (const float*)d_in[3];   // [192]
    const float* bhh1 = (const float*)d_in[4];   // [192]
    const float* Wih2 = (const float*)d_in[5];   // [96,64]
    const float* Whh2 = (const float*)d_in[6];   // [96,32]
    const float* bih2 = (const float*)d_in[7];   // [96]
    const float* bhh2 = (const float*)d_in[8];   // [96]
    float* out = (float*)d_out;                  // [1024,32]

    gru2_fused_kernel<<<NBATCH / NB, NTHREADS>>>(
        x, Wih1, Whh1, bih1, bhh1, Wih2, Whh2, bih2, bhh2, out);
}

// round 14
// speedup vs baseline: 1.0042x; 1.0042x over previous
#include <cuda_runtime.h>
#include <cstdint>

// 2-layer GRU encoder, fused. R11: homogeneous thread pool (no warp
// specialization): every thread does layer-1 phase then layer-2 phase per step,
// separated by plain __syncthreads(). Butterfly shfl reductions (redux.f32 is
// not supported on sm_103). Weights stay in registers, f32x2 FMA throughout.
// B=1024, T=1024, H1=64, H2=32. Grid 256 x 256 threads, 2 CTAs/SM, NB=4.

#define T_STEPS 1024
#define NBATCH  1024
#define H1DIM   64
#define H2DIM   32
#define NB      4      // batch rows per block
#define NTHREADS 256

__device__ __forceinline__ void fma2(uint64_t &acc, uint64_t a, uint64_t b) {
    asm("fma.rn.f32x2 %0, %1, %2, %0;" : "+l"(acc) : "l"(a), "l"(b));
}
__device__ __forceinline__ float hadd2(uint64_t v) {
    float lo, hi;
    asm("mov.b64 {%0,%1}, %2;" : "=f"(lo), "=f"(hi) : "l"(v));
    return lo + hi;
}
__device__ __forceinline__ float sigf(float x) {
    return __fdividef(1.0f, 1.0f + __expf(-x));
}
__device__ __forceinline__ float tanhf_fast(float x) {
    return fmaf(2.0f, sigf(2.0f * x), -1.0f);   // safe at both infinities
}

__global__ void __launch_bounds__(NTHREADS, 2)
gru2_fused_kernel(const float* __restrict__ x,
                  const float* __restrict__ Wih1, const float* __restrict__ Whh1,
                  const float* __restrict__ bih1, const float* __restrict__ bhh1,
                  const float* __restrict__ Wih2, const float* __restrict__ Whh2,
                  const float* __restrict__ bih2, const float* __restrict__ bhh2,
                  float* __restrict__ out)
{
    __shared__ __align__(16) float xs[NB][T_STEPS];      // 16 KB x slab
    __shared__ __align__(16) float h1s[2][NB][H1DIM];    // double-buffered h1
    __shared__ __align__(16) float h2s[2][NB][H2DIM];    // double-buffered h2

    const int tid = threadIdx.x;
    const int b0  = blockIdx.x * NB;

    // ---- phase-1 identity: (j, kq) ; k pairs {kq + 4p}, p in [0,8) ----
    const int kq = tid & 3;
    const int j  = tid >> 2;
    // ---- phase-2 identity: (j2, s) ; k pairs {s + 8p} ----
    const int s  = tid & 7;
    const int j2 = tid >> 3;

    // --- load x slab (coalesced float4) + zero h buffers ---
    for (int i = tid; i < NB * T_STEPS / 4; i += NTHREADS) {
        int row = i / (T_STEPS / 4);
        int col = i % (T_STEPS / 4);
        reinterpret_cast<float4*>(xs[row])[col] =
            reinterpret_cast<const float4*>(x + (size_t)(b0 + row) * T_STEPS)[col];
    }
    for (int i = tid; i < 2 * NB * H1DIM; i += NTHREADS) (&h1s[0][0][0])[i] = 0.0f;
    for (int i = tid; i < 2 * NB * H2DIM; i += NTHREADS) (&h2s[0][0][0])[i] = 0.0f;

    // ---- weights in registers ----
    // layer 1: rows (j, j+64, j+128) of Whh1, pairs {kq+4p}
    uint64_t w1[3][8];
    #pragma unroll
    for (int g = 0; g < 3; g++) {
        const float* row = Whh1 + (size_t)(j + 64 * g) * 64;
        #pragma unroll
        for (int p = 0; p < 8; p++)
            w1[g][p] = *reinterpret_cast<const uint64_t*>(row + 2 * (kq + 4 * p));
    }
    const float wir = Wih1[j], wiz = Wih1[j + 64], win = Wih1[j + 128];
    const float br  = bih1[j]      + bhh1[j];
    const float bz  = bih1[j + 64] + bhh1[j + 64];
    const float bni = bih1[j + 128];
    const float bnh = bhh1[j + 128];

    // layer 2: rows (j2, j2+32, j2+64); ih pairs {s+8p} p<4, hh pairs {s+8p} p<2
    uint64_t wI[3][4], wH[3][2];
    #pragma unroll
    for (int g = 0; g < 3; g++) {
        const float* ri = Wih2 + (size_t)(j2 + 32 * g) * 64;
        #pragma unroll
        for (int p = 0; p < 4; p++)
            wI[g][p] = *reinterpret_cast<const uint64_t*>(ri + 2 * (s + 8 * p));
        const float* rh = Whh2 + (size_t)(j2 + 32 * g) * 32;
        #pragma unroll
        for (int p = 0; p < 2; p++)
            wH[g][p] = *reinterpret_cast<const uint64_t*>(rh + 2 * (s + 8 * p));
    }
    const float br2  = bih2[j2]      + bhh2[j2];
    const float bz2  = bih2[j2 + 32] + bhh2[j2 + 32];
    const float bn2i = bih2[j2 + 64];
    const float bn2h = bhh2[j2 + 64];

    __syncthreads();

    int rp = 0, q = 0;
    for (int it = 0; it < T_STEPS; ++it) {
        // ================= PHASE 1: layer-1 step it =================
        // reads h1s[rp] (= out1[it-1]), writes h1s[rp^1] (= out1[it])
        #pragma unroll 2
        for (int b = 0; b < NB; b++) {
            uint64_t aR = 0, aZ = 0, aN = 0;
            #pragma unroll
            for (int p = 0; p < 8; p++) {
                uint64_t hv = *reinterpret_cast<const uint64_t*>(
                    &h1s[rp][b][2 * (kq + 4 * p)]);
                fma2(aR, w1[0][p], hv);
                fma2(aZ, w1[1][p], hv);
                fma2(aN, w1[2][p], hv);
            }
            float sR = hadd2(aR);
            sR += __shfl_xor_sync(0xffffffffu, sR, 1);
            sR += __shfl_xor_sync(0xffffffffu, sR, 2);
            float sZ = hadd2(aZ);
            sZ += __shfl_xor_sync(0xffffffffu, sZ, 1);
            sZ += __shfl_xor_sync(0xffffffffu, sZ, 2);
            float sN = hadd2(aN);
            sN += __shfl_xor_sync(0xffffffffu, sN, 1);
            sN += __shfl_xor_sync(0xffffffffu, sN, 2);
            if (kq == b) {                 // one lane per (j, b) finalizes
                float xv  = xs[b][it];
                float r   = sigf(fmaf(wir, xv, sR + br));
                float z   = sigf(fmaf(wiz, xv, sZ + bz));
                float gxn = fmaf(win, xv, bni);
                float n   = tanhf_fast(fmaf(r, sN + bnh, gxn));
                float ho  = h1s[rp][b][j];
                h1s[rp ^ 1][b][j] = n + z * (ho - n);
            }
        }
        __syncthreads();

        // ================= PHASE 2: layer-2 step it =================
        // reads h1s[rp^1] (= out1[it]) and h2s[q], writes h2s[q^1]
        #pragma unroll 2
        for (int b = 0; b < NB; b++) {
            uint64_t aR = 0, aZ = 0, aNI = 0, aNH = 0;
            #pragma unroll
            for (int p = 0; p < 4; p++) {
                uint64_t hv = *reinterpret_cast<const uint64_t*>(
                    &h1s[rp ^ 1][b][2 * (s + 8 * p)]);
                fma2(aR,  wI[0][p], hv);
                fma2(aZ,  wI[1][p], hv);
                fma2(aNI, wI[2][p], hv);
            }
            #pragma unroll
            for (int p = 0; p < 2; p++) {
                uint64_t hv = *reinterpret_cast<const uint64_t*>(
                    &h2s[q][b][2 * (s + 8 * p)]);
                fma2(aR,  wH[0][p], hv);
                fma2(aZ,  wH[1][p], hv);
                fma2(aNH, wH[2][p], hv);
            }
            float sR  = hadd2(aR);
            sR  += __shfl_xor_sync(0xffffffffu, sR, 1);
            sR  += __shfl_xor_sync(0xffffffffu, sR, 2);
            sR  += __shfl_xor_sync(0xffffffffu, sR, 4);
            float sZ  = hadd2(aZ);
            sZ  += __shfl_xor_sync(0xffffffffu, sZ, 1);
            sZ  += __shfl_xor_sync(0xffffffffu, sZ, 2);
            sZ  += __shfl_xor_sync(0xffffffffu, sZ, 4);
            float sNI = hadd2(aNI);
            sNI += __shfl_xor_sync(0xffffffffu, sNI, 1);
            sNI += __shfl_xor_sync(0xffffffffu, sNI, 2);
            sNI += __shfl_xor_sync(0xffffffffu, sNI, 4);
            float sNH = hadd2(aNH);
            sNH += __shfl_xor_sync(0xffffffffu, sNH, 1);
            sNH += __shfl_xor_sync(0xffffffffu, sNH, 2);
            sNH += __shfl_xor_sync(0xffffffffu, sNH, 4);
            if (s == b) {                  // one lane per (j2, b) finalizes
                float r  = sigf(sR + br2);
                float z  = sigf(sZ + bz2);
                float n  = tanhf_fast(sNI + bn2i + r * (sNH + bn2h));
                float ho = h2s[q][b][j2];
                float hn = n + z * (ho - n);
                h2s[q ^ 1][b][j2] = hn;
                if (it == T_STEPS - 1)
                    out[(size_t)(b0 + b) * H2DIM + j2] = hn;
            }
        }
        __syncthreads();

        rp ^= 1;
        q  ^= 1;
    }
}

extern "C" void kernel_launch(void* const* d_in, const int* in_sizes, int n_in,
                              void* d_out, int out_size) {
    const float* x    = (const float*)d_in[0];   // [1024,1024]
    const float* Wih1 = (const float*)d_in[1];   // [192,1]
    const float* Whh1 = (const float*)d_in[2];   // [192,64]
    const float* bih1 = (const float*)d_in[3];   // [192]
    const float* bhh1 = (const float*)d_in[4];   // [192]
    const float* Wih2 = (const float*)d_in[5];   // [96,64]
    const float* Whh2 = (const float*)d_in[6];   // [96,32]
    const float* bih2 = (const float*)d_in[7];   // [96]
    const float* bhh2 = (const float*)d_in[8];   // [96]
    float* out = (float*)d_out;                  // [1024,32]

    gru2_fused_kernel<<<NBATCH / NB, NTHREADS>>>(
        x, Wih1, Whh1, bih1, bhh1, Wih2, Whh2, bih2, bhh2, out);
}

// round 15
// speedup vs baseline: 1.0052x; 1.0011x over previous
#include <cuda_runtime.h>
#include <cstdint>

// 2-layer GRU encoder, fused. R11: homogeneous thread pool (no warp
// specialization): every thread does layer-1 phase then layer-2 phase per step,
// separated by plain __syncthreads(). Butterfly shfl reductions (redux.f32 is
// not supported on sm_103). Weights stay in registers, f32x2 FMA throughout.
// B=1024, T=1024, H1=64, H2=32. Grid 256 x 256 threads, 2 CTAs/SM, NB=4.

#define T_STEPS 1024
#define NBATCH  1024
#define H1DIM   64
#define H2DIM   32
#define NB      4      // batch rows per block
#define NTHREADS 256

__device__ __forceinline__ void fma2(uint64_t &acc, uint64_t a, uint64_t b) {
    asm("fma.rn.f32x2 %0, %1, %2, %0;" : "+l"(acc) : "l"(a), "l"(b));
}
__device__ __forceinline__ float hadd2(uint64_t v) {
    float lo, hi;
    asm("mov.b64 {%0,%1}, %2;" : "=f"(lo), "=f"(hi) : "l"(v));
    return lo + hi;
}
__device__ __forceinline__ float sigf(float x) {
    return __fdividef(1.0f, 1.0f + __expf(-x));
}
__device__ __forceinline__ float tanhf_fast(float x) {
    return fmaf(2.0f, sigf(2.0f * x), -1.0f);   // safe at both infinities
}

__global__ void __launch_bounds__(NTHREADS, 2)
gru2_fused_kernel(const float* __restrict__ x,
                  const float* __restrict__ Wih1, const float* __restrict__ Whh1,
                  const float* __restrict__ bih1, const float* __restrict__ bhh1,
                  const float* __restrict__ Wih2, const float* __restrict__ Whh2,
                  const float* __restrict__ bih2, const float* __restrict__ bhh2,
                  float* __restrict__ out)
{
    __shared__ __align__(16) float xs[NB][T_STEPS];      // 16 KB x slab
    __shared__ __align__(16) float h1s[2][NB][H1DIM];    // double-buffered h1
    __shared__ __align__(16) float h2s[2][NB][H2DIM];    // double-buffered h2

    const int tid = threadIdx.x;
    const int b0  = blockIdx.x * NB;

    // ---- phase-1 identity: (j, kq) ; k pairs {kq + 4p}, p in [0,8) ----
    const int kq = tid & 3;
    const int j  = tid >> 2;
    // ---- phase-2 identity: (j2, s) ; k pairs {s + 8p} ----
    const int s  = tid & 7;
    const int j2 = tid >> 3;

    // --- load x slab (coalesced float4) + zero h buffers ---
    for (int i = tid; i < NB * T_STEPS / 4; i += NTHREADS) {
        int row = i / (T_STEPS / 4);
        int col = i % (T_STEPS / 4);
        reinterpret_cast<float4*>(xs[row])[col] =
            reinterpret_cast<const float4*>(x + (size_t)(b0 + row) * T_STEPS)[col];
    }
    for (int i = tid; i < 2 * NB * H1DIM; i += NTHREADS) (&h1s[0][0][0])[i] = 0.0f;
    for (int i = tid; i < 2 * NB * H2DIM; i += NTHREADS) (&h2s[0][0][0])[i] = 0.0f;

    // ---- weights in registers ----
    // layer 1: rows (j, j+64, j+128) of Whh1, pairs {kq+4p}
    uint64_t w1[3][8];
    #pragma unroll
    for (int g = 0; g < 3; g++) {
        const float* row = Whh1 + (size_t)(j + 64 * g) * 64;
        #pragma unroll
        for (int p = 0; p < 8; p++)
            w1[g][p] = *reinterpret_cast<const uint64_t*>(row + 2 * (kq + 4 * p));
    }
    const float wir = Wih1[j], wiz = Wih1[j + 64], win = Wih1[j + 128];
    const float br  = bih1[j]      + bhh1[j];
    const float bz  = bih1[j + 64] + bhh1[j + 64];
    const float bni = bih1[j + 128];
    const float bnh = bhh1[j + 128];

    // layer 2: rows (j2, j2+32, j2+64); ih pairs {s+8p} p<4, hh pairs {s+8p} p<2
    uint64_t wI[3][4], wH[3][2];
    #pragma unroll
    for (int g = 0; g < 3; g++) {
        const float* ri = Wih2 + (size_t)(j2 + 32 * g) * 64;
        #pragma unroll
        for (int p = 0; p < 4; p++)
            wI[g][p] = *reinterpret_cast<const uint64_t*>(ri + 2 * (s + 8 * p));
        const float* rh = Whh2 + (size_t)(j2 + 32 * g) * 32;
        #pragma unroll
        for (int p = 0; p < 2; p++)
            wH[g][p] = *reinterpret_cast<const uint64_t*>(rh + 2 * (s + 8 * p));
    }
    const float br2  = bih2[j2]      + bhh2[j2];
    const float bz2  = bih2[j2 + 32] + bhh2[j2 + 32];
    const float bn2i = bih2[j2 + 64];
    const float bn2h = bhh2[j2 + 64];

    __syncthreads();

    int rp = 0, q = 0;
    for (int it = 0; it < T_STEPS; ++it) {
        // ================= PHASE 1: layer-1 step it =================
        // reads h1s[rp] (= out1[it-1]), writes h1s[rp^1] (= out1[it])
        #pragma unroll 2
        for (int b = 0; b < NB; b++) {
            uint64_t aR = 0, aZ = 0, aN = 0;
            #pragma unroll
            for (int p = 0; p < 8; p++) {
                uint64_t hv = *reinterpret_cast<const uint64_t*>(
                    &h1s[rp][b][2 * (kq + 4 * p)]);
                fma2(aR, w1[0][p], hv);
                fma2(aZ, w1[1][p], hv);
                fma2(aN, w1[2][p], hv);
            }
            float sR = hadd2(aR);
            sR += __shfl_xor_sync(0xffffffffu, sR, 1);
            sR += __shfl_xor_sync(0xffffffffu, sR, 2);
            float sZ = hadd2(aZ);
            sZ += __shfl_xor_sync(0xffffffffu, sZ, 1);
            sZ += __shfl_xor_sync(0xffffffffu, sZ, 2);
            float sN = hadd2(aN);
            sN += __shfl_xor_sync(0xffffffffu, sN, 1);
            sN += __shfl_xor_sync(0xffffffffu, sN, 2);
            if (kq == b) {                 // one lane per (j, b) finalizes
                float xv  = xs[b][it];
                float r   = sigf(fmaf(wir, xv, sR + br));
                float z   = sigf(fmaf(wiz, xv, sZ + bz));
                float gxn = fmaf(win, xv, bni);
                float n   = tanhf_fast(fmaf(r, sN + bnh, gxn));
                float ho  = h1s[rp][b][j];
                h1s[rp ^ 1][b][j] = n + z * (ho - n);
            }
        }
        __syncthreads();

        // ================= PHASE 2: layer-2 step it =================
        // reads h1s[rp^1] (= out1[it]) and h2s[q], writes h2s[q^1]
        #pragma unroll 2
        for (int b = 0; b < NB; b++) {
            uint64_t aR = 0, aZ = 0, aNI = 0, aNH = 0;
            #pragma unroll
            for (int p = 0; p < 4; p++) {
                uint64_t hv = *reinterpret_cast<const uint64_t*>(
                    &h1s[rp ^ 1][b][2 * (s + 8 * p)]);
                fma2(aR,  wI[0][p], hv);
                fma2(aZ,  wI[1][p], hv);
                fma2(aNI, wI[2][p], hv);
            }
            #pragma unroll
            for (int p = 0; p < 2; p++) {
                uint64_t hv = *reinterpret_cast<const uint64_t*>(
                    &h2s[q][b][2 * (s + 8 * p)]);
                fma2(aR,  wH[0][p], hv);
                fma2(aZ,  wH[1][p], hv);
                fma2(aNH, wH[2][p], hv);
            }
            float sR  = hadd2(aR);
            sR  += __shfl_xor_sync(0xffffffffu, sR, 1);
            sR  += __shfl_xor_sync(0xffffffffu, sR, 2);
            sR  += __shfl_xor_sync(0xffffffffu, sR, 4);
            float sZ  = hadd2(aZ);
            sZ  += __shfl_xor_sync(0xffffffffu, sZ, 1);
            sZ  += __shfl_xor_sync(0xffffffffu, sZ, 2);
            sZ  += __shfl_xor_sync(0xffffffffu, sZ, 4);
            float sNI = hadd2(aNI);
            sNI += __shfl_xor_sync(0xffffffffu, sNI, 1);
            sNI += __shfl_xor_sync(0xffffffffu, sNI, 2);
            sNI += __shfl_xor_sync(0xffffffffu, sNI, 4);
            float sNH = hadd2(aNH);
            sNH += __shfl_xor_sync(0xffffffffu, sNH, 1);
            sNH += __shfl_xor_sync(0xffffffffu, sNH, 2);
            sNH += __shfl_xor_sync(0xffffffffu, sNH, 4);
            if (s == b) {                  // one lane per (j2, b) finalizes
                float r  = sigf(sR + br2);
                float z  = sigf(sZ + bz2);
                float n  = tanhf_fast(sNI + bn2i + r * (sNH + bn2h));
                float ho = h2s[q][b][j2];
                float hn = n + z * (ho - n);
                h2s[q ^ 1][b][j2] = hn;
                if (it == T_STEPS - 1)
                    out[(size_t)(b0 + b) * H2DIM + j2] = hn;
            }
        }
        __syncthreads();

        rp ^= 1;
        q  ^= 1;
    }
}

extern "C" void kernel_launch(void* const* d_in, const int* in_sizes, int n_in,
                              void* d_out, int out_size) {
    const float* x    = (const float*)d_in[0];   // [1024,1024]
    const float* Wih1 = (const float*)d_in[1];   // [192,1]
    const float* Whh1 = (const float*)d_in[2];   // [192,64]
    const float* bih1 = (const float*)d_in[3];   // [192]
    const float* bhh1 = (const float*)d_in[4];   // [192]
    const float* Wih2 = (const float*)d_in[5];   // [96,64]
    const float* Whh2 = (const float*)d_in[6];   // [96,32]
    const float* bih2 = (const float*)d_in[7];   // [96]
    const float* bhh2 = (const float*)d_in[8];   // [96]
    float* out = (float*)d_out;                  // [1024,32]

    gru2_fused_kernel<<<NBATCH / NB, NTHREADS>>>(
        x, Wih1, Whh1, bih1, bhh1, Wih2, Whh2, bih2, bhh2, out);
}

// round 16
// speedup vs baseline: 1.2711x; 1.2645x over previous
#include <cuda_runtime.h>
#include <cstdint>

// 2-layer GRU encoder, fused, warp-specialized (R9 structure), R16 changes:
//  - grid = 148 CTAs x 512 threads: exactly 1 CTA/SM, zero SM-load imbalance
//    (NB = 7 for CTAs 0..135, NB = 6 for CTAs 136..147; max 7 vs R9's 8)
//  - h loads via LDS.128 on chunk-of-4 interleaved k-slices (conflict-free)
//  - gate math in all lanes (butterfly gives full sums), store predicated
// Threads 0-255: layer 1. Threads 256-511: layer 2 (1 step behind).

#define T_STEPS 1024
#define H1DIM   64
#define H2DIM   32
#define NBMAX   7
#define NTHREADS 512
#define GRID    148

__device__ __forceinline__ void fma2(uint64_t &acc, uint64_t a, uint64_t b) {
    asm("fma.rn.f32x2 %0, %1, %2, %0;" : "+l"(acc) : "l"(a), "l"(b));
}
__device__ __forceinline__ float hadd2(uint64_t v) {
    float lo, hi;
    asm("mov.b64 {%0,%1}, %2;" : "=f"(lo), "=f"(hi) : "l"(v));
    return lo + hi;
}
__device__ __forceinline__ float sigf(float x) {
    return __fdividef(1.0f, 1.0f + __expf(-x));
}
__device__ __forceinline__ float tanhf_fast(float x) {
    return fmaf(2.0f, sigf(2.0f * x), -1.0f);   // safe at both infinities
}
__device__ __forceinline__ void barrier_all() {
    asm volatile("bar.sync 1, %0;" :: "n"(NTHREADS) : "memory");
}

__global__ void __launch_bounds__(NTHREADS, 1)
gru2_fused_kernel(const float* __restrict__ x,
                  const float* __restrict__ Wih1, const float* __restrict__ Whh1,
                  const float* __restrict__ bih1, const float* __restrict__ bhh1,
                  const float* __restrict__ Wih2, const float* __restrict__ Whh2,
                  const float* __restrict__ bih2, const float* __restrict__ bhh2,
                  float* __restrict__ out)
{
    __shared__ __align__(16) float xs[NBMAX][T_STEPS];      // 28 KB x slab
    __shared__ __align__(16) float h1s[2][NBMAX][H1DIM];    // double-buffered h1
    __shared__ __align__(16) float h2s[2][NBMAX][H2DIM];    // double-buffered h2

    const int tid = threadIdx.x;
    const int bid = blockIdx.x;
    const int nb  = (bid < 136) ? 7 : 6;
    const int b0  = (bid < 136) ? bid * 7 : 952 + (bid - 136) * 6;

    // --- load x slab (coalesced float4) + zero h buffers ---
    for (int i = tid; i < nb * (T_STEPS / 4); i += NTHREADS) {
        int row = i / (T_STEPS / 4);
        int col = i % (T_STEPS / 4);
        reinterpret_cast<float4*>(xs[row])[col] =
            reinterpret_cast<const float4*>(x + (size_t)(b0 + row) * T_STEPS)[col];
    }
    for (int i = tid; i < 2 * NBMAX * H1DIM; i += NTHREADS) (&h1s[0][0][0])[i] = 0.0f;
    for (int i = tid; i < 2 * NBMAX * H2DIM; i += NTHREADS) (&h2s[0][0][0])[i] = 0.0f;
    __syncthreads();

    if (tid < 256) {
        // ================= LAYER 1 =================
        // thread = (j, kq): j in [0,64), kq in [0,4). Owns 4-float chunks
        // {kq + 4c : c in [0,4)} of the k dim -> LDS.128, conflict-free.
        const int kq = tid & 3;
        const int j  = tid >> 2;

        ulonglong2 w1[3][4];
        #pragma unroll
        for (int g = 0; g < 3; g++) {
            const float* row = Whh1 + (size_t)(j + 64 * g) * 64;
            #pragma unroll
            for (int c = 0; c < 4; c++)
                w1[g][c] = *reinterpret_cast<const ulonglong2*>(row + 4 * (kq + 4 * c));
        }
        const float wir = Wih1[j], wiz = Wih1[j + 64], win = Wih1[j + 128];
        const float br  = bih1[j]      + bhh1[j];
        const float bz  = bih1[j + 64] + bhh1[j + 64];
        const float bni = bih1[j + 128];
        const float bnh = bhh1[j + 128];

        int rp = 0;
        for (int it = 0; it <= T_STEPS; ++it) {
            if (it < T_STEPS) {
                #pragma unroll
                for (int b = 0; b < NBMAX; b++) {
                    if (b >= nb) break;
                    uint64_t aR = 0, aZ = 0, aN = 0;
                    #pragma unroll
                    for (int c = 0; c < 4; c++) {
                        ulonglong2 hv = *reinterpret_cast<const ulonglong2*>(
                            &h1s[rp][b][4 * (kq + 4 * c)]);
                        fma2(aR, w1[0][c].x, hv.x); fma2(aR, w1[0][c].y, hv.y);
                        fma2(aZ, w1[1][c].x, hv.x); fma2(aZ, w1[1][c].y, hv.y);
                        fma2(aN, w1[2][c].x, hv.x); fma2(aN, w1[2][c].y, hv.y);
                    }
                    float sR = hadd2(aR);
                    sR += __shfl_xor_sync(0xffffffffu, sR, 1);
                    sR += __shfl_xor_sync(0xffffffffu, sR, 2);
                    float sZ = hadd2(aZ);
                    sZ += __shfl_xor_sync(0xffffffffu, sZ, 1);
                    sZ += __shfl_xor_sync(0xffffffffu, sZ, 2);
                    float sN = hadd2(aN);
                    sN += __shfl_xor_sync(0xffffffffu, sN, 1);
                    sN += __shfl_xor_sync(0xffffffffu, sN, 2);
                    // all lanes hold full sums; compute gates everywhere,
                    // store predicated (no branch -> no BSSY/BSYNC)
                    float xv  = xs[b][it];
                    float r   = sigf(fmaf(wir, xv, sR + br));
                    float z   = sigf(fmaf(wiz, xv, sZ + bz));
                    float gxn = fmaf(win, xv, bni);
                    float n   = tanhf_fast(fmaf(r, sN + bnh, gxn));
                    float ho  = h1s[rp][b][j];
                    float hn  = n + z * (ho - n);
                    if ((b & 3) == kq)
                        h1s[rp ^ 1][b][j] = hn;
                }
            }
            barrier_all();
            rp ^= 1;
        }
    } else {
        // ================= LAYER 2 (one step behind) =================
        // thread = (j2, s): j2 in [0,32), s in [0,8). ih chunks {s + 8c : c<2},
        // hh chunk {s}. Octet butterfly reduce (xor 1,2,4).
        const int t2 = tid - 256;
        const int s  = t2 & 7;
        const int j2 = t2 >> 3;

        ulonglong2 wI[3][2], wH[3];
        #pragma unroll
        for (int g = 0; g < 3; g++) {
            const float* ri = Wih2 + (size_t)(j2 + 32 * g) * 64;
            #pragma unroll
            for (int c = 0; c < 2; c++)
                wI[g][c] = *reinterpret_cast<const ulonglong2*>(ri + 4 * (s + 8 * c));
            const float* rh = Whh2 + (size_t)(j2 + 32 * g) * 32;
            wH[g] = *reinterpret_cast<const ulonglong2*>(rh + 4 * s);
        }
        const float br2  = bih2[j2]      + bhh2[j2];
        const float bz2  = bih2[j2 + 32] + bhh2[j2 + 32];
        const float bn2i = bih2[j2 + 64];
        const float bn2h = bhh2[j2 + 64];

        int rp = 0, q = 0;
        for (int it = 0; it <= T_STEPS; ++it) {
            if (it >= 1) {
                // processes step it-1: input out1[it-1] = h1s[rp], state h2s[q]
                #pragma unroll
                for (int b = 0; b < NBMAX; b++) {
                    if (b >= nb) break;
                    uint64_t aR = 0, aZ = 0, aNI = 0, aNH = 0;
                    #pragma unroll
                    for (int c = 0; c < 2; c++) {
                        ulonglong2 hv = *reinterpret_cast<const ulonglong2*>(
                            &h1s[rp][b][4 * (s + 8 * c)]);
                        fma2(aR,  wI[0][c].x, hv.x); fma2(aR,  wI[0][c].y, hv.y);
                        fma2(aZ,  wI[1][c].x, hv.x); fma2(aZ,  wI[1][c].y, hv.y);
                        fma2(aNI, wI[2][c].x, hv.x); fma2(aNI, wI[2][c].y, hv.y);
                    }
                    {
                        ulonglong2 hv = *reinterpret_cast<const ulonglong2*>(
                            &h2s[q][b][4 * s]);
                        fma2(aR,  wH[0].x, hv.x); fma2(aR,  wH[0].y, hv.y);
                        fma2(aZ,  wH[1].x, hv.x); fma2(aZ,  wH[1].y, hv.y);
                        fma2(aNH, wH[2].x, hv.x); fma2(aNH, wH[2].y, hv.y);
                    }
                    float sR  = hadd2(aR);
                    sR  += __shfl_xor_sync(0xffffffffu, sR, 1);
                    sR  += __shfl_xor_sync(0xffffffffu, sR, 2);
                    sR  += __shfl_xor_sync(0xffffffffu, sR, 4);
                    float sZ  = hadd2(aZ);
                    sZ  += __shfl_xor_sync(0xffffffffu, sZ, 1);
                    sZ  += __shfl_xor_sync(0xffffffffu, sZ, 2);
                    sZ  += __shfl_xor_sync(0xffffffffu, sZ, 4);
                    float sNI = hadd2(aNI);
                    sNI += __shfl_xor_sync(0xffffffffu, sNI, 1);
                    sNI += __shfl_xor_sync(0xffffffffu, sNI, 2);
                    sNI += __shfl_xor_sync(0xffffffffu, sNI, 4);
                    float sNH = hadd2(aNH);
                    sNH += __shfl_xor_sync(0xffffffffu, sNH, 1);
                    sNH += __shfl_xor_sync(0xffffffffu, sNH, 2);
                    sNH += __shfl_xor_sync(0xffffffffu, sNH, 4);
                    float r  = sigf(sR + br2);
                    float z  = sigf(sZ + bz2);
                    float n  = tanhf_fast(sNI + bn2i + r * (sNH + bn2h));
                    float ho = h2s[q][b][j2];
                    float hn = n + z * (ho - n);
                    if (s == b) {
                        h2s[q ^ 1][b][j2] = hn;
                        if (it == T_STEPS)
                            out[(size_t)(b0 + b) * H2DIM + j2] = hn;
                    }
                }
            }
            barrier_all();
            rp ^= 1;
            q  ^= 1;
        }
    }
}

extern "C" void kernel_launch(void* const* d_in, const int* in_sizes, int n_in,
                              void* d_out, int out_size) {
    const float* x    = (const float*)d_in[0];   // [1024,1024]
    const float* Wih1 = (const float*)d_in[1];   // [192,1]
    const float* Whh1 = (const float*)d_in[2];   // [192,64]
    const float* bih1 = (const float*)d_in[3];   // [192]
    const float* bhh1 = (const float*)d_in[4];   // [192]
    const float* Wih2 = (const float*)d_in[5];   // [96,64]
    const float* Whh2 = (const float*)d_in[6];   // [96,32]
    const float* bih2 = (const float*)d_in[7];   // [96]
    const float* bhh2 = (const float*)d_in[8];   // [96]
    float* out = (float*)d_out;                  // [1024,32]

    gru2_fused_kernel<<<GRID, NTHREADS>>>(
        x, Wih1, Whh1, bih1, bhh1, Wih2, Whh2, bih2, bhh2, out);
}